// round 1
// baseline (speedup 1.0000x reference)
#include <cuda_runtime.h>
#include <cuda_fp16.h>
#include <math.h>
#include <stdint.h>

// Problem constants
#define B_    512
#define TENC  140
#define E_    256
#define H_    512
#define O_    64
#define TOUT  280
#define ROWS_ENC (B_*TENC)   // 71680

// ---------------------------------------------------------------------------
// Device scratch (static globals; no runtime allocation allowed)
// ---------------------------------------------------------------------------
__device__ __half d_eh[2][B_ * 1024];        // [buf][row][0:512 e | 512:1024 h] fp16
__device__ float  d_h32[2][B_ * H_];         // fp32 hidden state, double buffered
__device__ __half d_Wg[3 * H_ * 1024];       // 1536 x 1024: [w_ih | w_hh] interleaved by K
__device__ __half d_WA[(H_ + O_) * H_];      // 576 x 512: [emb_W@out_W ; reg_W@out_W]
__device__ float  d_bA[H_ + O_];             // fused biases
__device__ __half d_x0[B_ * E_];             // x0 = encoder_outputs[:, -1, :] fp16
__device__ __half d_embW[H_ * E_];           // emb_W fp16 (step-0 path)
__device__ __half d_regW[O_ * E_];           // reg_W fp16 (encoder head)
__device__ __half d_enc16[(size_t)ROWS_ENC * E_]; // encoder outputs fp16

// ---------------------------------------------------------------------------
// mma.sync helpers (m16n8k16, f16 in, f32 acc)
// ---------------------------------------------------------------------------
__device__ __forceinline__ void mma16816(float c[4], const uint32_t a[4], const uint32_t b[2]) {
    asm volatile(
        "mma.sync.aligned.m16n8k16.row.col.f32.f16.f16.f32 "
        "{%0,%1,%2,%3}, {%4,%5,%6,%7}, {%8,%9}, {%0,%1,%2,%3};\n"
        : "+f"(c[0]), "+f"(c[1]), "+f"(c[2]), "+f"(c[3])
        : "r"(a[0]), "r"(a[1]), "r"(a[2]), "r"(a[3]), "r"(b[0]), "r"(b[1]));
}

// A fragment: rows (row0+grp, +8), cols (k0 + qp*2, +8). smem leading dim ld (halves).
__device__ __forceinline__ void load_a_frag(uint32_t a[4], const __half* As, int ld,
                                            int row0, int k0, int grp, int qp) {
    const __half* p = As + (row0 + grp) * ld + k0 + qp * 2;
    a[0] = *(const uint32_t*)(p);
    a[1] = *(const uint32_t*)(p + 8 * ld);
    a[2] = *(const uint32_t*)(p + 8);
    a[3] = *(const uint32_t*)(p + 8 * ld + 8);
}

// B fragment (col-major KxN == row n contiguous in k): n = n0+grp, k = k0+qp*2 (+8)
__device__ __forceinline__ void load_b_frag(uint32_t b[2], const __half* Bs, int ld,
                                            int n0, int k0, int grp, int qp) {
    const __half* p = Bs + (n0 + grp) * ld + k0 + qp * 2;
    b[0] = *(const uint32_t*)(p);
    b[1] = *(const uint32_t*)(p + 8);
}

__device__ __forceinline__ float sigf(float x) { return 1.0f / (1.0f + __expf(-x)); }

// ---------------------------------------------------------------------------
// prep: weight fusion + fp16 conversions (one launch)
// ---------------------------------------------------------------------------
__global__ void prep_kernel(const float* __restrict__ enc,  const float* __restrict__ ehid,
                            const float* __restrict__ embW, const float* __restrict__ embB,
                            const float* __restrict__ wih,  const float* __restrict__ whh,
                            const float* __restrict__ outW, const float* __restrict__ outB,
                            const float* __restrict__ regW, const float* __restrict__ regB) {
    const long long N0  = (long long)ROWS_ENC * E_;   // enc convert
    const long long N1  = N0 + (long long)B_ * E_;    // x0
    const long long N2  = N1 + 1536LL * 1024;         // Wg
    const long long N3  = N2 + 576LL * 512;           // WA
    const long long N3b = N3 + 576;                   // bA
    const long long N4  = N3b + (long long)O_ * E_;   // regW16
    const long long N5  = N4 + (long long)B_ * H_;    // h0
    const long long N6  = N5 + (long long)H_ * E_;    // embW16

    for (long long i = (long long)blockIdx.x * blockDim.x + threadIdx.x; i < N6;
         i += (long long)gridDim.x * blockDim.x) {
        if (i < N0) {
            d_enc16[i] = __float2half(enc[i]);
        } else if (i < N1) {
            long long k = i - N0; int b = (int)(k >> 8), c = (int)(k & 255);
            d_x0[k] = __float2half(enc[(long long)b * TENC * E_ + 139 * E_ + c]);
        } else if (i < N2) {
            long long k = i - N1; int j = (int)(k >> 10), c = (int)(k & 1023);
            float v = (c < 512) ? wih[j * 512 + c] : whh[j * 512 + c - 512];
            d_Wg[k] = __float2half(v);
        } else if (i < N3) {
            long long k = i - N2; int j = (int)(k >> 9), c = (int)(k & 511);
            float s = 0.f;
            if (j < 512) { for (int m = 0; m < E_; ++m) s += embW[j * E_ + m] * outW[m * H_ + c]; }
            else { int o = j - 512; for (int m = 0; m < E_; ++m) s += regW[o * E_ + m] * outW[m * H_ + c]; }
            d_WA[k] = __float2half(s);
        } else if (i < N3b) {
            int j = (int)(i - N3);
            float s = 0.f;
            if (j < 512) { for (int m = 0; m < E_; ++m) s += embW[j * E_ + m] * outB[m]; s += embB[j]; }
            else { int o = j - 512; for (int m = 0; m < E_; ++m) s += regW[o * E_ + m] * outB[m]; s += regB[o]; }
            d_bA[j] = s;
        } else if (i < N4) {
            long long k = i - N3b; d_regW[k] = __float2half(regW[k]);
        } else if (i < N5) {
            long long k = i - N4; int b = (int)(k >> 9), c = (int)(k & 511);
            float v = ehid[k];
            d_h32[0][k] = v;
            d_eh[0][b * 1024 + 512 + c] = __float2half(v);
        } else {
            long long k = i - N5; d_embW[k] = __float2half(embW[k]);
        }
    }
}

// ---------------------------------------------------------------------------
// Generic fp16 GEMM: C = A @ B^T + bias, epilogues: step (relu->e / dec rows) or enc
// BLK_M=64, BLK_N=32, BLK_K=32, 256 threads, warps 4x2 (warp tile 16x16)
// ---------------------------------------------------------------------------
__global__ __launch_bounds__(256) void gemmA_kernel(
    const __half* __restrict__ A, int lda,
    const __half* __restrict__ Bw, int ldb,
    const float* __restrict__ bias, int K,
    __half* __restrict__ e_out,       // step mode: write relu(acc+b) to cols<512 (stride 1024)
    float* __restrict__ dec_out,      // d_out base (both modes when used)
    int t_dec,                        // time index for dec columns (step mode)
    int enc_mode)                     // 1: encoder regression epilogue
{
    __shared__ __align__(16) __half As[64 * 40];
    __shared__ __align__(16) __half Bs[32 * 40];

    const int tid = threadIdx.x;
    const int m0 = blockIdx.y * 64, n0 = blockIdx.x * 32;
    const int lane = tid & 31, warp = tid >> 5;
    const int wm = warp >> 1, wn = warp & 1;
    const int grp = lane >> 2, qp = lane & 3;

    float c[2][4] = {};
    const int nch = K >> 5;

    for (int kc = 0; kc < nch; ++kc) {
        const int k0 = kc * 32;
        __syncthreads();
        { // A: 64 rows x 32 halves = 256 uint4
            int r = tid >> 2, v = tid & 3;
            *(uint4*)&As[r * 40 + v * 8] = *(const uint4*)&A[(size_t)(m0 + r) * lda + k0 + v * 8];
        }
        if (tid < 128) { // B: 32 rows x 32 halves = 128 uint4
            int r = tid >> 2, v = tid & 3;
            *(uint4*)&Bs[r * 40 + v * 8] = *(const uint4*)&Bw[(size_t)(n0 + r) * ldb + k0 + v * 8];
        }
        __syncthreads();
#pragma unroll
        for (int kk = 0; kk < 32; kk += 16) {
            uint32_t a[4];
            load_a_frag(a, As, 40, wm * 16, kk, grp, qp);
            uint32_t b[2];
            load_b_frag(b, Bs, 40, wn * 16 + 0, kk, grp, qp);
            mma16816(c[0], a, b);
            load_b_frag(b, Bs, 40, wn * 16 + 8, kk, grp, qp);
            mma16816(c[1], a, b);
        }
    }

    const int rbase = m0 + wm * 16 + grp;
    const int cbase = n0 + wn * 16 + qp * 2;
#pragma unroll
    for (int nb = 0; nb < 2; ++nb)
#pragma unroll
        for (int i = 0; i < 4; ++i) {
            int row = rbase + (i >> 1) * 8;
            int col = cbase + nb * 8 + (i & 1);
            float v = c[nb][i] + bias[col];
            if (enc_mode) {
                int b = row / 140, tt = row - b * 140;
                dec_out[(size_t)b * TOUT * O_ + tt * O_ + col] = v;
            } else if (col < H_) {
                e_out[(size_t)row * 1024 + col] = __float2half(fmaxf(v, 0.0f));
            } else {
                dec_out[(size_t)row * TOUT * O_ + t_dec * O_ + (col - H_)] = v;
            }
        }
}

// ---------------------------------------------------------------------------
// GRU step: fused [gi|gh] GEMM (K=1024, A=[e|h]) for r/z, split accumulators for
// the n gate, full gating epilogue -> h_{t+1} (fp32 + fp16 double buffered).
// grid (16, 8): n0 = bx*32 over H, m0 = by*64 over B.
// ---------------------------------------------------------------------------
__global__ __launch_bounds__(256) void gru_kernel(int cur,
                                                  const float* __restrict__ bih,
                                                  const float* __restrict__ bhh) {
    __shared__ __align__(16) __half As[64 * 40];
    __shared__ __align__(16) __half Bs[3][32 * 40];

    const __half* A = d_eh[cur];
    const int nxt = cur ^ 1;
    const int tid = threadIdx.x;
    const int m0 = blockIdx.y * 64, n0 = blockIdx.x * 32;
    const int lane = tid & 31, warp = tid >> 5;
    const int wm = warp >> 1, wn = warp & 1;
    const int grp = lane >> 2, qp = lane & 3;

    float cR[2][4] = {}, cZ[2][4] = {}, cNi[2][4] = {}, cNh[2][4] = {};

#pragma unroll
    for (int hf = 0; hf < 2; ++hf) {       // hf=0: e part (k<512), hf=1: h part
#pragma unroll 1
        for (int kc = 0; kc < 16; ++kc) {
            const int k0 = hf * 512 + kc * 32;
            __syncthreads();
            {
                int r = tid >> 2, v = tid & 3;
                *(uint4*)&As[r * 40 + v * 8] = *(const uint4*)&A[(size_t)(m0 + r) * 1024 + k0 + v * 8];
            }
            for (int i = tid; i < 384; i += 256) {
                int g = i >> 7, j = i & 127, r = j >> 2, v = j & 3;
                *(uint4*)&Bs[g][r * 40 + v * 8] =
                    *(const uint4*)&d_Wg[(size_t)(g * 512 + n0 + r) * 1024 + k0 + v * 8];
            }
            __syncthreads();
#pragma unroll
            for (int kk = 0; kk < 32; kk += 16) {
                uint32_t a[4];
                load_a_frag(a, As, 40, wm * 16, kk, grp, qp);
#pragma unroll
                for (int nb = 0; nb < 2; ++nb) {
                    uint32_t b[2];
                    load_b_frag(b, Bs[0], 40, wn * 16 + nb * 8, kk, grp, qp);
                    mma16816(cR[nb], a, b);
                    load_b_frag(b, Bs[1], 40, wn * 16 + nb * 8, kk, grp, qp);
                    mma16816(cZ[nb], a, b);
                    load_b_frag(b, Bs[2], 40, wn * 16 + nb * 8, kk, grp, qp);
                    if (hf == 0) mma16816(cNi[nb], a, b);
                    else         mma16816(cNh[nb], a, b);
                }
            }
        }
    }

    const float* h32c = d_h32[cur];
    float* h32n = d_h32[nxt];
    __half* ehn = d_eh[nxt];
    const int rbase = m0 + wm * 16 + grp;
    const int cbase = n0 + wn * 16 + qp * 2;
#pragma unroll
    for (int nb = 0; nb < 2; ++nb)
#pragma unroll
        for (int i = 0; i < 4; ++i) {
            int row = rbase + (i >> 1) * 8;
            int j = cbase + nb * 8 + (i & 1);
            float r = sigf(cR[nb][i] + bih[j] + bhh[j]);
            float z = sigf(cZ[nb][i] + bih[512 + j] + bhh[512 + j]);
            float nn = tanhf(cNi[nb][i] + bih[1024 + j] + r * (cNh[nb][i] + bhh[1024 + j]));
            float ho = h32c[row * 512 + j];
            float hv = (1.0f - z) * nn + z * ho;
            h32n[row * 512 + j] = hv;
            ehn[(size_t)row * 1024 + 512 + j] = __float2half(hv);
        }
}

// ---------------------------------------------------------------------------
// Launch sequence (all graph-capturable, default stream)
// ---------------------------------------------------------------------------
extern "C" void kernel_launch(void* const* d_in, const int* in_sizes, int n_in,
                              void* d_out, int out_size) {
    const float* enc  = (const float*)d_in[0];
    const float* ehid = (const float*)d_in[1];
    const float* embW = (const float*)d_in[2];
    const float* embB = (const float*)d_in[3];
    const float* wih  = (const float*)d_in[4];
    const float* whh  = (const float*)d_in[5];
    const float* bih  = (const float*)d_in[6];
    const float* bhh  = (const float*)d_in[7];
    const float* outW = (const float*)d_in[8];
    const float* outB = (const float*)d_in[9];
    const float* regW = (const float*)d_in[10];
    const float* regB = (const float*)d_in[11];
    float* out = (float*)d_out;

    void* sym;
    cudaGetSymbolAddress(&sym, d_eh);     __half* p_eh   = (__half*)sym;
    cudaGetSymbolAddress(&sym, d_x0);     __half* p_x0   = (__half*)sym;
    cudaGetSymbolAddress(&sym, d_embW);   __half* p_embW = (__half*)sym;
    cudaGetSymbolAddress(&sym, d_regW);   __half* p_regW = (__half*)sym;
    cudaGetSymbolAddress(&sym, d_WA);     __half* p_WA   = (__half*)sym;
    cudaGetSymbolAddress(&sym, d_bA);     float*  p_bA   = (float*)sym;
    cudaGetSymbolAddress(&sym, d_enc16);  __half* p_enc  = (__half*)sym;

    // 1) Prep: conversions + weight fusion
    prep_kernel<<<4096, 256>>>(enc, ehid, embW, embB, wih, whh, outW, outB, regW, regB);

    // 2) Encoder regression head: out[:, 0:140, :] (independent of RNN)
    gemmA_kernel<<<dim3(2, 1120), 256>>>(p_enc, E_, p_regW, E_, regB, E_,
                                         nullptr, out, 0, 1);

    // 3) Step 0: e0 = relu(x0 @ emb_W^T + emb_b)  (K=256)
    gemmA_kernel<<<dim3(16, 8), 256>>>(p_x0, E_, p_embW, E_, embB, E_,
                                       p_eh /* eh[0] */, nullptr, 0, 0);

    // 4) 140 GRU steps; phase A writes e_{t+1} and dec row 140+t directly to out
    for (int t = 0; t < 140; ++t) {
        gru_kernel<<<dim3(16, 8), 256>>>(t & 1, bih, bhh);
        int nb = (t + 1) & 1;
        gemmA_kernel<<<dim3(18, 8), 256>>>(p_eh + (size_t)nb * B_ * 1024 + 512, 1024,
                                           p_WA, 512, p_bA, 512,
                                           p_eh + (size_t)nb * B_ * 1024, out, 140 + t, 0);
    }
}

// round 2
// speedup vs baseline: 1.4444x; 1.4444x over previous
#include <cuda_runtime.h>
#include <cuda_fp16.h>
#include <math.h>
#include <stdint.h>

// Problem constants
#define B_    512
#define TENC  140
#define E_    256
#define H_    512
#define O_    64
#define TOUT  280
#define NSTEP 140
#define ROWS_ENC (B_*TENC)   // 71680

#define WG_LD 1032           // 1024 + 8 pad (bank-conflict-free fragment loads)
#define AS_LD 72             // 64 + 8 pad

// ---------------------------------------------------------------------------
// Device scratch (static globals; no runtime allocation allowed)
// ---------------------------------------------------------------------------
__device__ __half d_eh[2][B_ * 1024];        // [buf][row][0:512 e | 512:1024 h] fp16
__device__ float  d_h32[2][B_ * H_];         // fp32 hidden state, double buffered
__device__ __half d_Wg[3 * H_ * 1024];       // 1536 x 1024: [w_ih | w_hh] fused by K
__device__ __half d_WA[(H_ + O_) * H_];      // 576 x 512: [emb_W@out_W ; reg_W@out_W]
__device__ float  d_bA[H_ + O_];             // fused biases
__device__ __half d_x0[B_ * E_];             // x0 = encoder_outputs[:, -1, :] fp16
__device__ __half d_embW[H_ * E_];           // emb_W fp16 (step-0 path)
__device__ __half d_regW[O_ * E_];           // reg_W fp16 (encoder head)
__device__ __half d_enc16[(size_t)ROWS_ENC * E_]; // encoder outputs fp16

// Row-group barriers (8 groups of 16 CTAs), one cache line each
struct Bar { unsigned cnt; unsigned gen; unsigned pad[30]; };
__device__ Bar d_bars[8];

// ---------------------------------------------------------------------------
// mma.sync helpers (m16n8k16, f16 in, f32 acc)
// ---------------------------------------------------------------------------
__device__ __forceinline__ void mma16816(float c[4], const uint32_t a[4], const uint32_t b[2]) {
    asm volatile(
        "mma.sync.aligned.m16n8k16.row.col.f32.f16.f16.f32 "
        "{%0,%1,%2,%3}, {%4,%5,%6,%7}, {%8,%9}, {%0,%1,%2,%3};\n"
        : "+f"(c[0]), "+f"(c[1]), "+f"(c[2]), "+f"(c[3])
        : "r"(a[0]), "r"(a[1]), "r"(a[2]), "r"(a[3]), "r"(b[0]), "r"(b[1]));
}

__device__ __forceinline__ void load_a_frag(uint32_t a[4], const __half* As, int ld,
                                            int row0, int k0, int grp, int qp) {
    const __half* p = As + (row0 + grp) * ld + k0 + qp * 2;
    a[0] = *(const uint32_t*)(p);
    a[1] = *(const uint32_t*)(p + 8 * ld);
    a[2] = *(const uint32_t*)(p + 8);
    a[3] = *(const uint32_t*)(p + 8 * ld + 8);
}

__device__ __forceinline__ void load_b_frag(uint32_t b[2], const __half* Bs, int ld,
                                            int n0, int k0, int grp, int qp) {
    const __half* p = Bs + (n0 + grp) * ld + k0 + qp * 2;
    b[0] = *(const uint32_t*)(p);
    b[1] = *(const uint32_t*)(p + 8);
}

__device__ __forceinline__ float sigf(float x) { return 1.0f / (1.0f + __expf(-x)); }

// cp.async helpers
__device__ __forceinline__ void cp_async16(void* s, const void* g) {
    unsigned sa = (unsigned)__cvta_generic_to_shared(s);
    asm volatile("cp.async.ca.shared.global [%0], [%1], 16;\n" :: "r"(sa), "l"(g));
}
__device__ __forceinline__ void cp_commit() { asm volatile("cp.async.commit_group;\n"); }
__device__ __forceinline__ void cp_wait1()  { asm volatile("cp.async.wait_group 1;\n"); }
__device__ __forceinline__ void cp_wait0()  { asm volatile("cp.async.wait_group 0;\n"); }

// 16-CTA row-group barrier. target = monotonically increasing generation.
__device__ __forceinline__ void group_barrier(int rb, unsigned target) {
    __syncthreads();
    if (threadIdx.x == 0) {
        __threadfence();
        unsigned a = atomicAdd(&d_bars[rb].cnt, 1);
        if (a == 15) {
            d_bars[rb].cnt = 0;
            __threadfence();
            atomicAdd(&d_bars[rb].gen, 1);
        } else {
            unsigned g;
            do {
                __nanosleep(32);
                asm volatile("ld.volatile.global.u32 %0, [%1];" : "=r"(g) : "l"(&d_bars[rb].gen));
            } while (g < target);
        }
        __threadfence();
    }
    __syncthreads();
}

// ---------------------------------------------------------------------------
// prep: weight fusion + fp16 conversions + barrier reset (one launch)
// ---------------------------------------------------------------------------
__global__ void prep_kernel(const float* __restrict__ enc,  const float* __restrict__ ehid,
                            const float* __restrict__ embW, const float* __restrict__ embB,
                            const float* __restrict__ wih,  const float* __restrict__ whh,
                            const float* __restrict__ outW, const float* __restrict__ outB,
                            const float* __restrict__ regW, const float* __restrict__ regB) {
    long long gid0 = (long long)blockIdx.x * blockDim.x + threadIdx.x;
    if (gid0 < 8) { d_bars[gid0].cnt = 0; d_bars[gid0].gen = 0; }

    const long long N0  = (long long)ROWS_ENC * E_;   // enc convert
    const long long N1  = N0 + (long long)B_ * E_;    // x0
    const long long N2  = N1 + 1536LL * 1024;         // Wg
    const long long N3  = N2 + 576LL * 512;           // WA
    const long long N3b = N3 + 576;                   // bA
    const long long N4  = N3b + (long long)O_ * E_;   // regW16
    const long long N5  = N4 + (long long)B_ * H_;    // h0
    const long long N6  = N5 + (long long)H_ * E_;    // embW16

    for (long long i = gid0; i < N6; i += (long long)gridDim.x * blockDim.x) {
        if (i < N0) {
            d_enc16[i] = __float2half(enc[i]);
        } else if (i < N1) {
            long long k = i - N0; int b = (int)(k >> 8), c = (int)(k & 255);
            d_x0[k] = __float2half(enc[(long long)b * TENC * E_ + 139 * E_ + c]);
        } else if (i < N2) {
            long long k = i - N1; int j = (int)(k >> 10), c = (int)(k & 1023);
            float v = (c < 512) ? wih[j * 512 + c] : whh[j * 512 + c - 512];
            d_Wg[k] = __float2half(v);
        } else if (i < N3) {
            long long k = i - N2; int j = (int)(k >> 9), c = (int)(k & 511);
            float s = 0.f;
            if (j < 512) { for (int m = 0; m < E_; ++m) s += embW[j * E_ + m] * outW[m * H_ + c]; }
            else { int o = j - 512; for (int m = 0; m < E_; ++m) s += regW[o * E_ + m] * outW[m * H_ + c]; }
            d_WA[k] = __float2half(s);
        } else if (i < N3b) {
            int j = (int)(i - N3);
            float s = 0.f;
            if (j < 512) { for (int m = 0; m < E_; ++m) s += embW[j * E_ + m] * outB[m]; s += embB[j]; }
            else { int o = j - 512; for (int m = 0; m < E_; ++m) s += regW[o * E_ + m] * outB[m]; s += regB[o]; }
            d_bA[j] = s;
        } else if (i < N4) {
            long long k = i - N3b; d_regW[k] = __float2half(regW[k]);
        } else if (i < N5) {
            long long k = i - N4; int b = (int)(k >> 9), c = (int)(k & 511);
            float v = ehid[k];
            d_h32[0][k] = v;
            d_eh[0][b * 1024 + 512 + c] = __float2half(v);
        } else {
            long long k = i - N5; d_embW[k] = __float2half(embW[k]);
        }
    }
}

// ---------------------------------------------------------------------------
// Generic fp16 GEMM (used for the one-shot encoder head and e0)
// BLK_M=64, BLK_N=32, BLK_K=32, 256 threads, warps 4x2 (warp tile 16x16)
// ---------------------------------------------------------------------------
__global__ __launch_bounds__(256) void gemmA_kernel(
    const __half* __restrict__ A, int lda,
    const __half* __restrict__ Bw, int ldb,
    const float* __restrict__ bias, int K,
    __half* __restrict__ e_out, float* __restrict__ dec_out,
    int t_dec, int enc_mode)
{
    __shared__ __align__(16) __half As[64 * 40];
    __shared__ __align__(16) __half Bs[32 * 40];

    const int tid = threadIdx.x;
    const int m0 = blockIdx.y * 64, n0 = blockIdx.x * 32;
    const int lane = tid & 31, warp = tid >> 5;
    const int wm = warp >> 1, wn = warp & 1;
    const int grp = lane >> 2, qp = lane & 3;

    float c[2][4] = {};
    const int nch = K >> 5;

    for (int kc = 0; kc < nch; ++kc) {
        const int k0 = kc * 32;
        __syncthreads();
        { int r = tid >> 2, v = tid & 3;
          *(uint4*)&As[r * 40 + v * 8] = *(const uint4*)&A[(size_t)(m0 + r) * lda + k0 + v * 8]; }
        if (tid < 128) { int r = tid >> 2, v = tid & 3;
          *(uint4*)&Bs[r * 40 + v * 8] = *(const uint4*)&Bw[(size_t)(n0 + r) * ldb + k0 + v * 8]; }
        __syncthreads();
#pragma unroll
        for (int kk = 0; kk < 32; kk += 16) {
            uint32_t a[4];
            load_a_frag(a, As, 40, wm * 16, kk, grp, qp);
            uint32_t b[2];
            load_b_frag(b, Bs, 40, wn * 16 + 0, kk, grp, qp);
            mma16816(c[0], a, b);
            load_b_frag(b, Bs, 40, wn * 16 + 8, kk, grp, qp);
            mma16816(c[1], a, b);
        }
    }

    const int rbase = m0 + wm * 16 + grp;
    const int cbase = n0 + wn * 16 + qp * 2;
#pragma unroll
    for (int nb = 0; nb < 2; ++nb)
#pragma unroll
        for (int i = 0; i < 4; ++i) {
            int row = rbase + (i >> 1) * 8;
            int col = cbase + nb * 8 + (i & 1);
            float v = c[nb][i] + bias[col];
            if (enc_mode) {
                int b = row / 140, tt = row - b * 140;
                dec_out[(size_t)b * TOUT * O_ + tt * O_ + col] = v;
            } else if (col < H_) {
                e_out[(size_t)row * 1024 + col] = __float2half(fmaxf(v, 0.0f));
            } else {
                dec_out[(size_t)row * TOUT * O_ + t_dec * O_ + (col - H_)] = v;
            }
        }
}

// ---------------------------------------------------------------------------
// Persistent RNN kernel: 128 CTAs (8 row-groups x 16 col-CTAs), weights SMEM-
// resident for all 140 steps, cp.async double-buffered activations,
// 16-CTA group barriers between phases.
//
// CTA (rb, cb):
//   Phase B: gates for rows [rb*64,+64), j-cols [cb*32,+32), K=1024 -> h_{t+1}
//   Phase A (cb<12): [e|dec] for rows rb, out-cols [cb*48,+48), K=512
// ---------------------------------------------------------------------------
#define SMEM_WG_HALVES (3 * 32 * WG_LD)          // 99072
#define SMEM_AS_HALVES (2 * 64 * AS_LD)          // 9216
#define SMEM_WA_HALVES (2 * 48 * AS_LD)          // 6912
#define SMEM_TOTAL_BYTES ((SMEM_WG_HALVES + SMEM_AS_HALVES + SMEM_WA_HALVES) * 2)  // 230400

extern __shared__ __half sm_dyn[];

__global__ __launch_bounds__(256, 1) void persist_kernel(
    const float* __restrict__ bih, const float* __restrict__ bhh,
    float* __restrict__ out)
{
    __half (*Wg_s)[32][WG_LD] = (__half (*)[32][WG_LD])sm_dyn;
    __half (*As)[64][AS_LD]   = (__half (*)[64][AS_LD])(sm_dyn + SMEM_WG_HALVES);
    __half (*WAs)[48][AS_LD]  = (__half (*)[48][AS_LD])(sm_dyn + SMEM_WG_HALVES + SMEM_AS_HALVES);

    const int tid = threadIdx.x;
    const int cid = blockIdx.x;
    const int rb = cid >> 4, cb = cid & 15;
    const int lane = tid & 31, warp = tid >> 5;
    const int wm = warp >> 1, wn = warp & 1;
    const int grp = lane >> 2, qp = lane & 3;
    const int m0g = rb * 64;

    // ---- Load this CTA's weight slice once (96 rows x 1024 halves) ----
    for (int idx = tid; idx < 96 * 128; idx += 256) {
        int r = idx >> 7, v = idx & 127;
        int g = r >> 5, jr = r & 31;
        cp_async16(&Wg_s[g][jr][v * 8],
                   &d_Wg[(size_t)(g * 512 + cb * 32 + jr) * 1024 + v * 8]);
    }
    cp_commit(); cp_wait0(); __syncthreads();

    unsigned gen = 0;
    int cur = 0;
    for (int t = 0; t < NSTEP; ++t) {
        const int nxt = cur ^ 1;

        // ================= Phase B: gate GEMM + GRU epilogue ================
        {
            const __half* A = d_eh[cur];
            float cR[2][4] = {}, cZ[2][4] = {}, cNi[2][4] = {}, cNh[2][4] = {};

            // preload chunk 0 (64-wide K chunks; 16 chunks over K=1024)
            {
#pragma unroll
                for (int i = 0; i < 2; ++i) {
                    int idx = tid + i * 256;
                    int r = idx >> 3, v = idx & 7;
                    cp_async16(&As[0][r][v * 8], &A[(size_t)(m0g + r) * 1024 + v * 8]);
                }
                cp_commit();
            }
#pragma unroll 1
            for (int kc = 0; kc < 16; ++kc) {
                if (kc < 15) {
                    int buf = (kc + 1) & 1;
#pragma unroll
                    for (int i = 0; i < 2; ++i) {
                        int idx = tid + i * 256;
                        int r = idx >> 3, v = idx & 7;
                        cp_async16(&As[buf][r][v * 8],
                                   &A[(size_t)(m0g + r) * 1024 + (kc + 1) * 64 + v * 8]);
                    }
                    cp_commit(); cp_wait1();
                } else cp_wait0();
                __syncthreads();
                const __half* Asb = &As[kc & 1][0][0];
                const int kw = kc * 64;
#pragma unroll
                for (int kk = 0; kk < 64; kk += 16) {
                    uint32_t a[4];
                    load_a_frag(a, Asb, AS_LD, wm * 16, kk, grp, qp);
#pragma unroll
                    for (int nb = 0; nb < 2; ++nb) {
                        uint32_t b[2];
                        load_b_frag(b, &Wg_s[0][0][0], WG_LD, wn * 16 + nb * 8, kw + kk, grp, qp);
                        mma16816(cR[nb], a, b);
                        load_b_frag(b, &Wg_s[1][0][0], WG_LD, wn * 16 + nb * 8, kw + kk, grp, qp);
                        mma16816(cZ[nb], a, b);
                        load_b_frag(b, &Wg_s[2][0][0], WG_LD, wn * 16 + nb * 8, kw + kk, grp, qp);
                        if (kc < 8) mma16816(cNi[nb], a, b);
                        else        mma16816(cNh[nb], a, b);
                    }
                }
                __syncthreads();
            }

            const float* h32c = d_h32[cur];
            float* h32n = d_h32[nxt];
            __half* ehn = d_eh[nxt];
            const int rbase = m0g + wm * 16 + grp;
            const int jbase = cb * 32 + wn * 16 + qp * 2;
#pragma unroll
            for (int nb = 0; nb < 2; ++nb)
#pragma unroll
                for (int i = 0; i < 4; ++i) {
                    int row = rbase + (i >> 1) * 8;
                    int j = jbase + nb * 8 + (i & 1);
                    float r = sigf(cR[nb][i] + bih[j] + bhh[j]);
                    float z = sigf(cZ[nb][i] + bih[512 + j] + bhh[512 + j]);
                    float nn = tanhf(cNi[nb][i] + bih[1024 + j] + r * (cNh[nb][i] + bhh[1024 + j]));
                    float ho = h32c[row * 512 + j];
                    float hv = (1.0f - z) * nn + z * ho;
                    h32n[row * 512 + j] = hv;
                    ehn[(size_t)row * 1024 + 512 + j] = __float2half(hv);
                }
        }
        ++gen; group_barrier(rb, gen);

        // ============ Phase A: [e|dec] = h_{t+1} @ WA^T + bA ================
        if (cb < 12) {
            const __half* A = &d_eh[nxt][512];   // h half, row stride 1024
            float cc[3][4] = {};

            // preload chunk 0 (64-wide K chunks; 8 chunks over K=512)
            {
#pragma unroll
                for (int i = 0; i < 2; ++i) {
                    int idx = tid + i * 256;
                    int r = idx >> 3, v = idx & 7;
                    cp_async16(&As[0][r][v * 8], &A[(size_t)(m0g + r) * 1024 + v * 8]);
                    if (idx < 384)
                        cp_async16(&WAs[0][r][v * 8], &d_WA[(size_t)(cb * 48 + r) * 512 + v * 8]);
                }
                cp_commit();
            }
#pragma unroll 1
            for (int kc = 0; kc < 8; ++kc) {
                if (kc < 7) {
                    int buf = (kc + 1) & 1;
#pragma unroll
                    for (int i = 0; i < 2; ++i) {
                        int idx = tid + i * 256;
                        int r = idx >> 3, v = idx & 7;
                        cp_async16(&As[buf][r][v * 8],
                                   &A[(size_t)(m0g + r) * 1024 + (kc + 1) * 64 + v * 8]);
                        if (idx < 384)
                            cp_async16(&WAs[buf][r][v * 8],
                                       &d_WA[(size_t)(cb * 48 + r) * 512 + (kc + 1) * 64 + v * 8]);
                    }
                    cp_commit(); cp_wait1();
                } else cp_wait0();
                __syncthreads();
                const __half* Asb = &As[kc & 1][0][0];
                const __half* Wb  = &WAs[kc & 1][0][0];
#pragma unroll
                for (int kk = 0; kk < 64; kk += 16) {
                    uint32_t a[4];
                    load_a_frag(a, Asb, AS_LD, wm * 16, kk, grp, qp);
#pragma unroll
                    for (int nb = 0; nb < 3; ++nb) {
                        uint32_t b[2];
                        load_b_frag(b, Wb, AS_LD, wn * 24 + nb * 8, kk, grp, qp);
                        mma16816(cc[nb], a, b);
                    }
                }
                __syncthreads();
            }

            __half* ehn = d_eh[nxt];
            const int rbase = m0g + wm * 16 + grp;
            const int jl = wn * 24 + qp * 2;
#pragma unroll
            for (int nb = 0; nb < 3; ++nb)
#pragma unroll
                for (int i = 0; i < 4; ++i) {
                    int row = rbase + (i >> 1) * 8;
                    int j = cb * 48 + jl + nb * 8 + (i & 1);
                    float v = cc[nb][i] + d_bA[j];
                    if (j < 512) ehn[(size_t)row * 1024 + j] = __float2half(fmaxf(v, 0.0f));
                    else out[(size_t)row * TOUT * O_ + (140 + t) * O_ + (j - 512)] = v;
                }
        }
        ++gen; group_barrier(rb, gen);

        cur = nxt;
    }
}

// ---------------------------------------------------------------------------
// Launch sequence (graph-capturable, default stream)
// ---------------------------------------------------------------------------
extern "C" void kernel_launch(void* const* d_in, const int* in_sizes, int n_in,
                              void* d_out, int out_size) {
    const float* enc  = (const float*)d_in[0];
    const float* ehid = (const float*)d_in[1];
    const float* embW = (const float*)d_in[2];
    const float* embB = (const float*)d_in[3];
    const float* wih  = (const float*)d_in[4];
    const float* whh  = (const float*)d_in[5];
    const float* bih  = (const float*)d_in[6];
    const float* bhh  = (const float*)d_in[7];
    const float* outW = (const float*)d_in[8];
    const float* outB = (const float*)d_in[9];
    const float* regW = (const float*)d_in[10];
    const float* regB = (const float*)d_in[11];
    float* out = (float*)d_out;

    void* sym;
    cudaGetSymbolAddress(&sym, d_eh);    __half* p_eh   = (__half*)sym;
    cudaGetSymbolAddress(&sym, d_x0);    __half* p_x0   = (__half*)sym;
    cudaGetSymbolAddress(&sym, d_embW);  __half* p_embW = (__half*)sym;
    cudaGetSymbolAddress(&sym, d_regW);  __half* p_regW = (__half*)sym;
    cudaGetSymbolAddress(&sym, d_enc16); __half* p_enc  = (__half*)sym;

    cudaFuncSetAttribute(persist_kernel,
                         cudaFuncAttributeMaxDynamicSharedMemorySize, SMEM_TOTAL_BYTES);

    // 1) Prep: conversions + weight fusion + barrier reset
    prep_kernel<<<4096, 256>>>(enc, ehid, embW, embB, wih, whh, outW, outB, regW, regB);

    // 2) Encoder regression head: out[:, 0:140, :]
    gemmA_kernel<<<dim3(2, 1120), 256>>>(p_enc, E_, p_regW, E_, regB, E_,
                                         nullptr, out, 0, 1);

    // 3) Step 0: e0 = relu(x0 @ emb_W^T + emb_b)
    gemmA_kernel<<<dim3(16, 8), 256>>>(p_x0, E_, p_embW, E_, embB, E_,
                                       p_eh, nullptr, 0, 0);

    // 4) All 140 GRU steps in one persistent kernel
    persist_kernel<<<128, 256, SMEM_TOTAL_BYTES>>>(bih, bhh, out);
}

// round 3
// speedup vs baseline: 2.0038x; 1.3874x over previous
#include <cuda_runtime.h>
#include <cuda_fp16.h>
#include <math.h>
#include <stdint.h>

// Problem constants
#define B_    512
#define TENC  140
#define E_    256
#define H_    512
#define O_    64
#define TOUT  280
#define NSTEP 140
#define ROWS_ENC (B_*TENC)   // 71680

#define WG_LD 1032           // 1024 + 8 pad (4-bank shift per row -> LDSM conflict-free)
#define AS_LD 72             // 64 + 8 pad

// ---------------------------------------------------------------------------
// Device scratch (static globals; no runtime allocation allowed)
// ---------------------------------------------------------------------------
__device__ __half d_eh[2][B_ * 1024];        // [buf][row][0:512 e | 512:1024 h] fp16
__device__ float  d_h32[2][B_ * H_];         // fp32 hidden state, double buffered
__device__ __half d_Wg[3 * H_ * 1024];       // 1536 x 1024: [w_ih | w_hh] fused by K
__device__ __half d_WA[(H_ + O_) * H_];      // 576 x 512: [emb_W@out_W ; reg_W@out_W]
__device__ float  d_bA[H_ + O_];             // fused biases
__device__ __half d_x0[B_ * E_];             // x0 = encoder_outputs[:, -1, :] fp16
__device__ __half d_embW[H_ * E_];           // emb_W fp16 (step-0 path)
__device__ __half d_regW[O_ * E_];           // reg_W fp16 (encoder head)
__device__ __half d_enc16[(size_t)ROWS_ENC * E_]; // encoder outputs fp16

// Row-group barriers (8 groups of 16 CTAs), one cache line each
struct Bar { unsigned cnt; unsigned gen; unsigned pad[30]; };
__device__ Bar d_bars[8];

// ---------------------------------------------------------------------------
// mma / ldmatrix helpers
// ---------------------------------------------------------------------------
__device__ __forceinline__ void mma16816(float c[4], const uint32_t a[4], const uint32_t b[2]) {
    asm volatile(
        "mma.sync.aligned.m16n8k16.row.col.f32.f16.f16.f32 "
        "{%0,%1,%2,%3}, {%4,%5,%6,%7}, {%8,%9}, {%0,%1,%2,%3};\n"
        : "+f"(c[0]), "+f"(c[1]), "+f"(c[2]), "+f"(c[3])
        : "r"(a[0]), "r"(a[1]), "r"(a[2]), "r"(a[3]), "r"(b[0]), "r"(b[1]));
}

__device__ __forceinline__ void ldsm_x4(uint32_t r[4], uint32_t saddr) {
    asm volatile("ldmatrix.sync.aligned.m8n8.x4.shared.b16 {%0,%1,%2,%3}, [%4];"
                 : "=r"(r[0]), "=r"(r[1]), "=r"(r[2]), "=r"(r[3]) : "r"(saddr));
}
__device__ __forceinline__ void ldsm_x2(uint32_t r[2], uint32_t saddr) {
    asm volatile("ldmatrix.sync.aligned.m8n8.x2.shared.b16 {%0,%1}, [%2];"
                 : "=r"(r[0]), "=r"(r[1]) : "r"(saddr));
}

// legacy scalar frag loads (for the one-shot gemmA kernel)
__device__ __forceinline__ void load_a_frag(uint32_t a[4], const __half* As, int ld,
                                            int row0, int k0, int grp, int qp) {
    const __half* p = As + (row0 + grp) * ld + k0 + qp * 2;
    a[0] = *(const uint32_t*)(p);
    a[1] = *(const uint32_t*)(p + 8 * ld);
    a[2] = *(const uint32_t*)(p + 8);
    a[3] = *(const uint32_t*)(p + 8 * ld + 8);
}
__device__ __forceinline__ void load_b_frag(uint32_t b[2], const __half* Bs, int ld,
                                            int n0, int k0, int grp, int qp) {
    const __half* p = Bs + (n0 + grp) * ld + k0 + qp * 2;
    b[0] = *(const uint32_t*)(p);
    b[1] = *(const uint32_t*)(p + 8);
}

__device__ __forceinline__ float sigf(float x) { return 1.0f / (1.0f + __expf(-x)); }

// cp.async helpers
__device__ __forceinline__ void cp_async16(void* s, const void* g) {
    unsigned sa = (unsigned)__cvta_generic_to_shared(s);
    asm volatile("cp.async.ca.shared.global [%0], [%1], 16;\n" :: "r"(sa), "l"(g));
}
__device__ __forceinline__ void cp_commit() { asm volatile("cp.async.commit_group;\n"); }
__device__ __forceinline__ void cp_wait0()  { asm volatile("cp.async.wait_group 0;\n"); }

// 16-CTA row-group barrier. target = monotonically increasing generation.
__device__ __forceinline__ void group_barrier(int rb, unsigned target) {
    __syncthreads();
    if (threadIdx.x == 0) {
        __threadfence();
        unsigned a = atomicAdd(&d_bars[rb].cnt, 1);
        if (a == 15) {
            d_bars[rb].cnt = 0;
            __threadfence();
            atomicAdd(&d_bars[rb].gen, 1);
        } else {
            unsigned g;
            do {
                __nanosleep(32);
                asm volatile("ld.volatile.global.u32 %0, [%1];" : "=r"(g) : "l"(&d_bars[rb].gen));
            } while (g < target);
        }
        __threadfence();
    }
    __syncthreads();
}

// ---------------------------------------------------------------------------
// prep: weight fusion + fp16 conversions + barrier reset (one launch)
// ---------------------------------------------------------------------------
__global__ void prep_kernel(const float* __restrict__ enc,  const float* __restrict__ ehid,
                            const float* __restrict__ embW, const float* __restrict__ embB,
                            const float* __restrict__ wih,  const float* __restrict__ whh,
                            const float* __restrict__ outW, const float* __restrict__ outB,
                            const float* __restrict__ regW, const float* __restrict__ regB) {
    long long gid0 = (long long)blockIdx.x * blockDim.x + threadIdx.x;
    if (gid0 < 8) { d_bars[gid0].cnt = 0; d_bars[gid0].gen = 0; }

    const long long N0  = (long long)ROWS_ENC * E_;
    const long long N1  = N0 + (long long)B_ * E_;
    const long long N2  = N1 + 1536LL * 1024;
    const long long N3  = N2 + 576LL * 512;
    const long long N3b = N3 + 576;
    const long long N4  = N3b + (long long)O_ * E_;
    const long long N5  = N4 + (long long)B_ * H_;
    const long long N6  = N5 + (long long)H_ * E_;

    for (long long i = gid0; i < N6; i += (long long)gridDim.x * blockDim.x) {
        if (i < N0) {
            d_enc16[i] = __float2half(enc[i]);
        } else if (i < N1) {
            long long k = i - N0; int b = (int)(k >> 8), c = (int)(k & 255);
            d_x0[k] = __float2half(enc[(long long)b * TENC * E_ + 139 * E_ + c]);
        } else if (i < N2) {
            long long k = i - N1; int j = (int)(k >> 10), c = (int)(k & 1023);
            float v = (c < 512) ? wih[j * 512 + c] : whh[j * 512 + c - 512];
            d_Wg[k] = __float2half(v);
        } else if (i < N3) {
            long long k = i - N2; int j = (int)(k >> 9), c = (int)(k & 511);
            float s = 0.f;
            if (j < 512) { for (int m = 0; m < E_; ++m) s += embW[j * E_ + m] * outW[m * H_ + c]; }
            else { int o = j - 512; for (int m = 0; m < E_; ++m) s += regW[o * E_ + m] * outW[m * H_ + c]; }
            d_WA[k] = __float2half(s);
        } else if (i < N3b) {
            int j = (int)(i - N3);
            float s = 0.f;
            if (j < 512) { for (int m = 0; m < E_; ++m) s += embW[j * E_ + m] * outB[m]; s += embB[j]; }
            else { int o = j - 512; for (int m = 0; m < E_; ++m) s += regW[o * E_ + m] * outB[m]; s += regB[o]; }
            d_bA[j] = s;
        } else if (i < N4) {
            long long k = i - N3b; d_regW[k] = __float2half(regW[k]);
        } else if (i < N5) {
            long long k = i - N4; int b = (int)(k >> 9), c = (int)(k & 511);
            float v = ehid[k];
            d_h32[0][k] = v;
            d_eh[0][b * 1024 + 512 + c] = __float2half(v);
        } else {
            long long k = i - N5; d_embW[k] = __float2half(embW[k]);
        }
    }
}

// ---------------------------------------------------------------------------
// Generic fp16 GEMM (one-shot encoder head and e0)
// ---------------------------------------------------------------------------
__global__ __launch_bounds__(256) void gemmA_kernel(
    const __half* __restrict__ A, int lda,
    const __half* __restrict__ Bw, int ldb,
    const float* __restrict__ bias, int K,
    __half* __restrict__ e_out, float* __restrict__ dec_out,
    int t_dec, int enc_mode)
{
    __shared__ __align__(16) __half As[64 * 40];
    __shared__ __align__(16) __half Bs[32 * 40];

    const int tid = threadIdx.x;
    const int m0 = blockIdx.y * 64, n0 = blockIdx.x * 32;
    const int lane = tid & 31, warp = tid >> 5;
    const int wm = warp >> 1, wn = warp & 1;
    const int grp = lane >> 2, qp = lane & 3;

    float c[2][4] = {};
    const int nch = K >> 5;

    for (int kc = 0; kc < nch; ++kc) {
        const int k0 = kc * 32;
        __syncthreads();
        { int r = tid >> 2, v = tid & 3;
          *(uint4*)&As[r * 40 + v * 8] = *(const uint4*)&A[(size_t)(m0 + r) * lda + k0 + v * 8]; }
        if (tid < 128) { int r = tid >> 2, v = tid & 3;
          *(uint4*)&Bs[r * 40 + v * 8] = *(const uint4*)&Bw[(size_t)(n0 + r) * ldb + k0 + v * 8]; }
        __syncthreads();
#pragma unroll
        for (int kk = 0; kk < 32; kk += 16) {
            uint32_t a[4];
            load_a_frag(a, As, 40, wm * 16, kk, grp, qp);
            uint32_t b[2];
            load_b_frag(b, Bs, 40, wn * 16 + 0, kk, grp, qp);
            mma16816(c[0], a, b);
            load_b_frag(b, Bs, 40, wn * 16 + 8, kk, grp, qp);
            mma16816(c[1], a, b);
        }
    }

    const int rbase = m0 + wm * 16 + grp;
    const int cbase = n0 + wn * 16 + qp * 2;
#pragma unroll
    for (int nb = 0; nb < 2; ++nb)
#pragma unroll
        for (int i = 0; i < 4; ++i) {
            int row = rbase + (i >> 1) * 8;
            int col = cbase + nb * 8 + (i & 1);
            float v = c[nb][i] + bias[col];
            if (enc_mode) {
                int b = row / 140, tt = row - b * 140;
                dec_out[(size_t)b * TOUT * O_ + tt * O_ + col] = v;
            } else if (col < H_) {
                e_out[(size_t)row * 1024 + col] = __float2half(fmaxf(v, 0.0f));
            } else {
                dec_out[(size_t)row * TOUT * O_ + t_dec * O_ + (col - H_)] = v;
            }
        }
}

// ---------------------------------------------------------------------------
// Persistent RNN kernel: 128 CTAs (8 row-groups x 16 col-CTAs), weights SMEM-
// resident, ldmatrix fragments, single-sync-per-chunk cp.async pipeline.
// ---------------------------------------------------------------------------
#define SMEM_WG_HALVES (3 * 32 * WG_LD)          // 99072
#define SMEM_AS_HALVES (2 * 64 * AS_LD)          // 9216
#define SMEM_WA_HALVES (2 * 48 * AS_LD)          // 6912
#define SMEM_TOTAL_BYTES ((SMEM_WG_HALVES + SMEM_AS_HALVES + SMEM_WA_HALVES) * 2)  // 230400

extern __shared__ __half sm_dyn[];

__global__ __launch_bounds__(256, 1) void persist_kernel(
    const float* __restrict__ bih, const float* __restrict__ bhh,
    float* __restrict__ out)
{
    __half (*Wg_s)[32][WG_LD] = (__half (*)[32][WG_LD])sm_dyn;
    __half (*As)[64][AS_LD]   = (__half (*)[64][AS_LD])(sm_dyn + SMEM_WG_HALVES);
    __half (*WAs)[48][AS_LD]  = (__half (*)[48][AS_LD])(sm_dyn + SMEM_WG_HALVES + SMEM_AS_HALVES);

    const int tid = threadIdx.x;
    const int cid = blockIdx.x;
    const int rb = cid >> 4, cb = cid & 15;
    const int lane = tid & 31, warp = tid >> 5;
    const int wm = warp >> 1, wn = warp & 1;
    const int grp = lane >> 2, qp = lane & 3;
    const int m0g = rb * 64;

    // shared-space base addresses for ldmatrix
    const uint32_t as_base  = (uint32_t)__cvta_generic_to_shared(&As[0][0][0]);
    const uint32_t wg_base  = (uint32_t)__cvta_generic_to_shared(&Wg_s[0][0][0]);
    const uint32_t was_base = (uint32_t)__cvta_generic_to_shared(&WAs[0][0][0]);

    // per-thread ldmatrix row offsets (in halves)
    const int aoff = (wm * 16 + (lane & 15)) * AS_LD + ((lane >> 4) << 3);
    int boff[3];
#pragma unroll
    for (int g = 0; g < 3; ++g)
        boff[g] = (g * 32 + wn * 16 + ((lane >> 4) << 3) + (lane & 7)) * WG_LD
                + (((lane >> 3) & 1) << 3);
    const int waoff4 = (wn * 24 + ((lane >> 4) << 3) + (lane & 7)) * AS_LD
                     + (((lane >> 3) & 1) << 3);
    const int l15 = lane & 15;
    const int waoff2 = (wn * 24 + 16 + (l15 & 7)) * AS_LD + ((l15 >> 3) << 3);

    // ---- Load this CTA's weight slice once (96 rows x 1024 halves) ----
    for (int idx = tid; idx < 96 * 128; idx += 256) {
        int r = idx >> 7, v = idx & 127;
        int g = r >> 5, jr = r & 31;
        cp_async16(&Wg_s[g][jr][v * 8],
                   &d_Wg[(size_t)(g * 512 + cb * 32 + jr) * 1024 + v * 8]);
    }
    cp_commit(); cp_wait0(); __syncthreads();

    unsigned gen = 0;
    int cur = 0;
    for (int t = 0; t < NSTEP; ++t) {
        const int nxt = cur ^ 1;

        // ================= Phase B: gate GEMM + GRU epilogue ================
        {
            const __half* A = d_eh[cur];
            float cR[2][4] = {}, cZ[2][4] = {}, cNi[2][4] = {}, cNh[2][4] = {};

            // preload chunk 0
#pragma unroll
            for (int i = 0; i < 2; ++i) {
                int idx = tid + i * 256;
                int r = idx >> 3, v = idx & 7;
                cp_async16(&As[0][r][v * 8], &A[(size_t)(m0g + r) * 1024 + v * 8]);
            }
            cp_commit();

#pragma unroll 1
            for (int kc = 0; kc < 16; ++kc) {
                cp_wait0();
                __syncthreads();
                if (kc < 15) {
                    int buf = (kc + 1) & 1;
#pragma unroll
                    for (int i = 0; i < 2; ++i) {
                        int idx = tid + i * 256;
                        int r = idx >> 3, v = idx & 7;
                        cp_async16(&As[buf][r][v * 8],
                                   &A[(size_t)(m0g + r) * 1024 + (kc + 1) * 64 + v * 8]);
                    }
                    cp_commit();
                }
                const uint32_t abase = as_base + (uint32_t)((kc & 1) * 64 * AS_LD) * 2;
                const int kw = kc * 64;
#pragma unroll
                for (int kk = 0; kk < 64; kk += 16) {
                    uint32_t a[4], b0[4], b1[4], b2[4];
                    ldsm_x4(a,  abase + (uint32_t)(aoff + kk) * 2);
                    ldsm_x4(b0, wg_base + (uint32_t)(boff[0] + kw + kk) * 2);
                    ldsm_x4(b1, wg_base + (uint32_t)(boff[1] + kw + kk) * 2);
                    ldsm_x4(b2, wg_base + (uint32_t)(boff[2] + kw + kk) * 2);
                    mma16816(cR[0], a, b0 + 0); mma16816(cR[1], a, b0 + 2);
                    mma16816(cZ[0], a, b1 + 0); mma16816(cZ[1], a, b1 + 2);
                    if (kc < 8) { mma16816(cNi[0], a, b2 + 0); mma16816(cNi[1], a, b2 + 2); }
                    else        { mma16816(cNh[0], a, b2 + 0); mma16816(cNh[1], a, b2 + 2); }
                }
            }

            const float* h32c = d_h32[cur];
            float* h32n = d_h32[nxt];
            __half* ehn = d_eh[nxt];
            const int rbase = m0g + wm * 16 + grp;
            const int jbase = cb * 32 + wn * 16 + qp * 2;
#pragma unroll
            for (int nb = 0; nb < 2; ++nb)
#pragma unroll
                for (int i = 0; i < 4; ++i) {
                    int row = rbase + (i >> 1) * 8;
                    int j = jbase + nb * 8 + (i & 1);
                    float r = sigf(cR[nb][i] + bih[j] + bhh[j]);
                    float z = sigf(cZ[nb][i] + bih[512 + j] + bhh[512 + j]);
                    float nn = tanhf(cNi[nb][i] + bih[1024 + j] + r * (cNh[nb][i] + bhh[1024 + j]));
                    float ho = h32c[row * 512 + j];
                    float hv = (1.0f - z) * nn + z * ho;
                    h32n[row * 512 + j] = hv;
                    ehn[(size_t)row * 1024 + 512 + j] = __float2half(hv);
                }
        }
        ++gen; group_barrier(rb, gen);

        // ============ Phase A: [e|dec] = h_{t+1} @ WA^T + bA ================
        if (cb < 12) {
            const __half* A = &d_eh[nxt][512];   // h half, row stride 1024
            float cc[3][4] = {};

            // preload chunk 0 (As + WAs, one group)
#pragma unroll
            for (int i = 0; i < 2; ++i) {
                int idx = tid + i * 256;
                int r = idx >> 3, v = idx & 7;
                cp_async16(&As[0][r][v * 8], &A[(size_t)(m0g + r) * 1024 + v * 8]);
                if (idx < 384)
                    cp_async16(&WAs[0][r][v * 8], &d_WA[(size_t)(cb * 48 + r) * 512 + v * 8]);
            }
            cp_commit();

#pragma unroll 1
            for (int kc = 0; kc < 8; ++kc) {
                cp_wait0();
                __syncthreads();
                if (kc < 7) {
                    int buf = (kc + 1) & 1;
#pragma unroll
                    for (int i = 0; i < 2; ++i) {
                        int idx = tid + i * 256;
                        int r = idx >> 3, v = idx & 7;
                        cp_async16(&As[buf][r][v * 8],
                                   &A[(size_t)(m0g + r) * 1024 + (kc + 1) * 64 + v * 8]);
                        if (idx < 384)
                            cp_async16(&WAs[buf][r][v * 8],
                                       &d_WA[(size_t)(cb * 48 + r) * 512 + (kc + 1) * 64 + v * 8]);
                    }
                    cp_commit();
                }
                const uint32_t abase = as_base + (uint32_t)((kc & 1) * 64 * AS_LD) * 2;
                const uint32_t wbase = was_base + (uint32_t)((kc & 1) * 48 * AS_LD) * 2;
#pragma unroll
                for (int kk = 0; kk < 64; kk += 16) {
                    uint32_t a[4], bw[4], bw2[2];
                    ldsm_x4(a,  abase + (uint32_t)(aoff + kk) * 2);
                    ldsm_x4(bw, wbase + (uint32_t)(waoff4 + kk) * 2);
                    ldsm_x2(bw2, wbase + (uint32_t)(waoff2 + kk) * 2);
                    mma16816(cc[0], a, bw + 0);
                    mma16816(cc[1], a, bw + 2);
                    mma16816(cc[2], a, bw2);
                }
            }

            __half* ehn = d_eh[nxt];
            const int rbase = m0g + wm * 16 + grp;
            const int jl = wn * 24 + qp * 2;
#pragma unroll
            for (int nb = 0; nb < 3; ++nb)
#pragma unroll
                for (int i = 0; i < 4; ++i) {
                    int row = rbase + (i >> 1) * 8;
                    int j = cb * 48 + jl + nb * 8 + (i & 1);
                    float v = cc[nb][i] + d_bA[j];
                    if (j < 512) ehn[(size_t)row * 1024 + j] = __float2half(fmaxf(v, 0.0f));
                    else out[(size_t)row * TOUT * O_ + (140 + t) * O_ + (j - 512)] = v;
                }
        }
        ++gen; group_barrier(rb, gen);

        cur = nxt;
    }
}

// ---------------------------------------------------------------------------
// Launch sequence (graph-capturable, default stream)
// ---------------------------------------------------------------------------
extern "C" void kernel_launch(void* const* d_in, const int* in_sizes, int n_in,
                              void* d_out, int out_size) {
    const float* enc  = (const float*)d_in[0];
    const float* ehid = (const float*)d_in[1];
    const float* embW = (const float*)d_in[2];
    const float* embB = (const float*)d_in[3];
    const float* wih  = (const float*)d_in[4];
    const float* whh  = (const float*)d_in[5];
    const float* bih  = (const float*)d_in[6];
    const float* bhh  = (const float*)d_in[7];
    const float* outW = (const float*)d_in[8];
    const float* outB = (const float*)d_in[9];
    const float* regW = (const float*)d_in[10];
    const float* regB = (const float*)d_in[11];
    float* out = (float*)d_out;

    void* sym;
    cudaGetSymbolAddress(&sym, d_eh);    __half* p_eh   = (__half*)sym;
    cudaGetSymbolAddress(&sym, d_x0);    __half* p_x0   = (__half*)sym;
    cudaGetSymbolAddress(&sym, d_embW);  __half* p_embW = (__half*)sym;
    cudaGetSymbolAddress(&sym, d_regW);  __half* p_regW = (__half*)sym;
    cudaGetSymbolAddress(&sym, d_enc16); __half* p_enc  = (__half*)sym;

    cudaFuncSetAttribute(persist_kernel,
                         cudaFuncAttributeMaxDynamicSharedMemorySize, SMEM_TOTAL_BYTES);

    // 1) Prep: conversions + weight fusion + barrier reset
    prep_kernel<<<4096, 256>>>(enc, ehid, embW, embB, wih, whh, outW, outB, regW, regB);

    // 2) Encoder regression head: out[:, 0:140, :]
    gemmA_kernel<<<dim3(2, 1120), 256>>>(p_enc, E_, p_regW, E_, regB, E_,
                                         nullptr, out, 0, 1);

    // 3) Step 0: e0 = relu(x0 @ emb_W^T + emb_b)
    gemmA_kernel<<<dim3(16, 8), 256>>>(p_x0, E_, p_embW, E_, embB, E_,
                                       p_eh, nullptr, 0, 0);

    // 4) All 140 GRU steps in one persistent kernel
    persist_kernel<<<128, 256, SMEM_TOTAL_BYTES>>>(bih, bhh, out);
}